// round 16
// baseline (speedup 1.0000x reference)
#include <cuda_runtime.h>
#include <cuda_bf16.h>
#include <cstdint>

// Problem constants (K=256, N=65536 fixed)
#define KDIM    256
#define NTIME   65536
#define NCHUNK  512
#define CHUNKL  128
#define WARMUP  32

#define NTILES  1024          // tiles of 64 output columns
#define TSTEP   148
#define GRID    148           // single wave, persistent tiles

#define CS      36            // u32 (bf16-pair) per k-chunk in permuted smem
#define RS      144           // u32 per row (4 chunks x 36); 576B, 16B-multiple
#define EPIS    68            // floats per row of epilogue staging (mult of 4)

// u32 offsets in dynamic smem
#define OFF_A    0            // [256][RS] u32 = 36864
#define OFF_S    36864        // [64][RS]  u32 = 9216
#define OFF_EPI  46080        // [128][EPIS] floats = 8704
#define OFF_MU   54784        // 256
#define OFF_RED  55040        // 512
#define SMEM_U32 55552
#define SMEM_BYTES (SMEM_U32 * 4)   // 222208 B

// Scratch (device globals; zero-initialized at module load)
__device__ __align__(16) __nv_bfloat16 g_S[(size_t)NTIME * KDIM]; // S[t][k]; row t=0 stays 0
__device__ float g_Mu0[KDIM];
__device__ float g_rowpart[NCHUNK * KDIM];
__device__ float g_partLL[GRID];
__device__ unsigned g_scanCnt;
__device__ unsigned g_gemmCnt;

__device__ __forceinline__ uint32_t pack_bf16(float lo, float hi) {
    __nv_bfloat162 p = __floats2bfloat162_rn(lo, hi);
    return *reinterpret_cast<uint32_t*>(&p);
}

// ---------------------------------------------------------------------------
// Kernel 1: chunked exponential scan (WARMUP makes chunks independent; decay
// <= e^-1 so carry error <= e^-32). Stores bf16 S at t = j+1, coalesced in k.
// Last-arriving block computes Mu0 (deterministic fixed-order sum).
// ---------------------------------------------------------------------------
__global__ __launch_bounds__(256) void scan_kernel(const float* __restrict__ obs,
                                                   const float* __restrict__ Beta) {
    int k = threadIdx.x;
    int c = blockIdx.x;
    float beta  = Beta[k];
    float decay = expf(-beta);

    const float* orow = obs + ((size_t)k << 16);
    int j0 = c << 7;

    float h = 0.f;
    if (c > 0) {
        const float4* wp = (const float4*)(orow + j0 - WARMUP);
        #pragma unroll
        for (int i = 0; i < WARMUP / 4; ++i) {
            float4 v = wp[i];
            h = decay * (h + v.x); h = decay * (h + v.y);
            h = decay * (h + v.z); h = decay * (h + v.w);
        }
    }

    float s = 0.f;
    const float4* mp = (const float4*)(orow + j0);
    __nv_bfloat16* srow = g_S + (((size_t)(j0 + 1)) << 8) + k;
    int nstore = 65535 - j0; if (nstore > CHUNKL) nstore = CHUNKL;

    #pragma unroll 4
    for (int q = 0; q < CHUNKL / 4; ++q) {
        float4 v = mp[q];
        float vv[4] = {v.x, v.y, v.z, v.w};
        #pragma unroll
        for (int e = 0; e < 4; ++e) {
            float o = vv[e];
            s += o;
            h = decay * (h + o);
            int i = (q << 2) + e;
            if (i < nstore) srow[(size_t)i << 8] = __float2bfloat16_rn(beta * h);
        }
    }
    g_rowpart[(c << 8) + k] = s;

    // last-arriving block computes Mu0
    __threadfence();
    __shared__ unsigned lastFlag;
    if (k == 0) lastFlag = atomicAdd(&g_scanCnt, 1);
    __syncthreads();
    if (lastFlag == NCHUNK - 1) {
        float t = 0.f;
        for (int cc = 0; cc < NCHUNK; ++cc) t += g_rowpart[(cc << 8) + k];
        g_Mu0[k] = t * (1.0f / (float)NTIME) / 10.0f + 0.01f;
        if (k == 0) g_scanCnt = 0;
    }
}

// ---------------------------------------------------------------------------
// Kernel 2: fused bf16 MMA GEMM + softplus + lams1 stores + loglik.
// Phase0 bulk-writes lams0 (Mu0 broadcast) with full vectorization.
// One CTA/SM, M=256, N=64 per tile, K=256, 8x2 warp grid (32x32 warp tiles).
// Last CTA performs the final deterministic double-precision loglik sum,
// adding the exact closed-form -NTIME * sum(Mu0) term.
// ---------------------------------------------------------------------------
__device__ __forceinline__ void mma_bf16(float* d, uint32_t a0, uint32_t a1,
                                         uint32_t a2, uint32_t a3,
                                         uint32_t b0, uint32_t b1) {
    asm volatile(
        "mma.sync.aligned.m16n8k16.row.col.f32.bf16.bf16.f32 "
        "{%0,%1,%2,%3}, {%4,%5,%6,%7}, {%8,%9}, {%0,%1,%2,%3};"
        : "+f"(d[0]), "+f"(d[1]), "+f"(d[2]), "+f"(d[3])
        : "r"(a0), "r"(a1), "r"(a2), "r"(a3), "r"(b0), "r"(b1));
}

__global__ __launch_bounds__(512, 1) void gemm_kernel(const float* __restrict__ obs,
                                                      const float* __restrict__ Alpha,
                                                      float* __restrict__ out) {
    extern __shared__ uint32_t smu[];
    uint32_t* As  = smu + OFF_A;                // [256][RS] bf16-pairs, permuted
    uint32_t* Ss  = smu + OFF_S;                // [64][RS]
    float*    epi = (float*)(smu + OFF_EPI);    // [128][EPIS]
    float*   Mu0s = (float*)(smu + OFF_MU);
    float*    red = (float*)(smu + OFF_RED);

    int tid   = threadIdx.x;
    int tile0 = blockIdx.x;

    // ---- Stage full Alpha into smem (bf16 pairs, permuted), once.
    {
        int r = tid >> 1, half = tid & 1;
        const float4* src = (const float4*)(Alpha + ((size_t)r << 8)) + half * 32;
        uint32_t* dst = As + r * RS;
        #pragma unroll
        for (int i = 0; i < 32; ++i) {
            int f = half * 32 + i;              // float4 idx: k = 4f..4f+3, pairs 2f, 2f+1
            float4 v = src[i];
            int j0 = 2 * f, j1 = 2 * f + 1;
            dst[(j0 & 3) * CS + (j0 >> 2)] = pack_bf16(v.x, v.y);
            dst[(j1 & 3) * CS + (j1 >> 2)] = pack_bf16(v.z, v.w);
        }
    }
    if (tid < 256) Mu0s[tid] = g_Mu0[tid];

    // ---- Phase0: bulk-write lams0 = broadcast(Mu0) with full vectorization.
    for (int r = blockIdx.x; r < KDIM; r += GRID) {
        float mu = g_Mu0[r];
        float* p = out + 1 + (((size_t)r) << 16) + tid * 128;
        float4 m4 = make_float4(mu, mu, mu, mu);
        p[0] = mu; p[1] = mu; p[2] = mu;
        #pragma unroll
        for (int i = 0; i < 31; ++i) *(float4*)(p + 3 + 4 * i) = m4;
        p[127] = mu;
    }

    int warp = tid >> 5, lane = tid & 31;
    int wm = warp & 7, wn = warp >> 3;          // 8x2 warp grid: 32x32 warp tiles
    int g  = lane >> 2, t = lane & 3;
    const uint32_t* aB = As + (wm * 32 + g) * RS + t * CS;
    const uint32_t* bB = Ss + (wn * 32 + g) * RS + t * CS;

    // ---- S tile register prefetch: 64 rows x 128 u32; 8 threads/row, 4 uint4 each.
    int scol = tid >> 3, sq = tid & 7;
    uint4 v[4];
    {
        const uint4* src = (const uint4*)g_S + ((size_t)(tile0 * 64 + scol) * 32) + sq * 4;
        #pragma unroll
        for (int i = 0; i < 4; ++i) v[i] = src[i];
    }

    int erow = tid >> 2;                        // epilogue row 0..127 within half
    int seg  = (tid & 3) << 4;                  // 16-col contiguous span

    float la0 = 0.f, la1 = 0.f;                 // split loglik accumulators

    for (int tile = tile0; tile < NTILES; tile += TSTEP) {
        __syncthreads();                        // prev epi/Ss reads done
        // STS prefetched S tile (permuted)
        {
            uint32_t* dst = Ss + scol * RS;
            #pragma unroll
            for (int i = 0; i < 4; ++i) {
                int u = 4 * sq + i;
                dst[u]          = v[i].x;
                dst[CS + u]     = v[i].y;
                dst[2 * CS + u] = v[i].z;
                dst[3 * CS + u] = v[i].w;
            }
        }
        __syncthreads();
        int ntile = tile + TSTEP;
        if (ntile < NTILES) {                   // overlap next LDG with MMA
            const uint4* src = (const uint4*)g_S + ((size_t)(ntile * 64 + scol) * 32) + sq * 4;
            #pragma unroll
            for (int i = 0; i < 4; ++i) v[i] = src[i];
        }
        // L2 prefetch of this tile's obs block (256 rows x 2 x 128B lines)
        asm volatile("prefetch.global.L2 [%0];" ::
                     "l"(obs + (((size_t)(tid >> 1)) << 16) + (tile << 6) + ((tid & 1) << 5)));

        float acc[2][4][4];
        #pragma unroll
        for (int mt = 0; mt < 2; ++mt)
            #pragma unroll
            for (int nt = 0; nt < 4; ++nt)
                #pragma unroll
                for (int q = 0; q < 4; ++q) acc[mt][nt][q] = 0.f;

        #pragma unroll
        for (int q = 0; q < 8; ++q) {           // each q = 2 k16 blocks
            uint4 Ag[2], Ah[2], Bn[4];
            #pragma unroll
            for (int mt = 0; mt < 2; ++mt) {
                Ag[mt] = *(const uint4*)(aB + (mt * 16) * RS + 4 * q);
                Ah[mt] = *(const uint4*)(aB + (mt * 16 + 8) * RS + 4 * q);
            }
            #pragma unroll
            for (int nt = 0; nt < 4; ++nt)
                Bn[nt] = *(const uint4*)(bB + (nt * 8) * RS + 4 * q);
            #pragma unroll
            for (int mt = 0; mt < 2; ++mt)
                #pragma unroll
                for (int nt = 0; nt < 4; ++nt) {
                    mma_bf16(acc[mt][nt], Ag[mt].x, Ah[mt].x, Ag[mt].y, Ah[mt].y,
                             Bn[nt].x, Bn[nt].y);
                    mma_bf16(acc[mt][nt], Ag[mt].z, Ah[mt].z, Ag[mt].w, Ah[mt].w,
                             Bn[nt].z, Bn[nt].w);
                }
        }

        // ---- Two half-passes: stage acc rows into epi buffer, stream epilogue.
        #pragma unroll
        for (int hp = 0; hp < 2; ++hp) {
            if (hp) __syncthreads();            // hp0 stream reads done before hp1 stage
            if ((wm >> 2) == hp) {              // stage: rows (wm&3)*32 + mt*16 + rr*8 + g
                int lr = (wm & 3) * 32 + g;
                #pragma unroll
                for (int mt = 0; mt < 2; ++mt)
                    #pragma unroll
                    for (int rr = 0; rr < 2; ++rr) {
                        int r = lr + mt * 16 + rr * 8;
                        #pragma unroll
                        for (int nt = 0; nt < 4; ++nt) {
                            int col = wn * 32 + nt * 8 + 2 * t;
                            *(float2*)(epi + r * EPIS + col) =
                                make_float2(acc[mt][nt][rr * 2], acc[mt][nt][rr * 2 + 1]);
                        }
                    }
            }
            __syncthreads();

            // Coalesced streaming epilogue: 16 contiguous columns per thread.
            int row = hp * 128 + erow;
            float mu = Mu0s[row];
            size_t grow = ((size_t)row) << 16;
            int t0 = (tile << 6) + seg;
            const float* esrc = epi + erow * EPIS + seg;

            float lam[16];
            #pragma unroll
            for (int i = 0; i < 4; ++i) {
                float4 xv = *(const float4*)(esrc + (i << 2));
                float xs[4] = {xv.x, xv.y, xv.z, xv.w};
                #pragma unroll
                for (int e = 0; e < 4; ++e) {
                    float x = xs[e];                      // x >= 0
                    lam[(i << 2) + e] = x + __logf(1.0f + __expf(-x));
                }
            }
            if (tile == 0 && seg == 0) lam[0] = 0.f;      // column t=0: lams1 = 0

            const float4* op = (const float4*)(obs + grow + t0);
            #pragma unroll
            for (int i = 0; i < 4; ++i) {
                float4 ov = op[i];
                la0 += ov.x * __logf(mu + lam[(i << 2) + 0] + 1e-5f) - lam[(i << 2) + 0];
                la1 += ov.y * __logf(mu + lam[(i << 2) + 1] + 1e-5f) - lam[(i << 2) + 1];
                la0 += ov.z * __logf(mu + lam[(i << 2) + 2] + 1e-5f) - lam[(i << 2) + 2];
                la1 += ov.w * __logf(mu + lam[(i << 2) + 3] + 1e-5f) - lam[(i << 2) + 3];
            }

            float* p1 = out + 1 + (((size_t)KDIM) << 16) + grow + t0;  // lams1
            // p1 is (16B-4) aligned: 3 scalars, 3x float4, 1 scalar.
            p1[0] = lam[0]; p1[1] = lam[1]; p1[2] = lam[2];
            *(float4*)(p1 + 3)  = make_float4(lam[3],  lam[4],  lam[5],  lam[6]);
            *(float4*)(p1 + 7)  = make_float4(lam[7],  lam[8],  lam[9],  lam[10]);
            *(float4*)(p1 + 11) = make_float4(lam[11], lam[12], lam[13], lam[14]);
            p1[15] = lam[15];
        }
    }

    // ---- Deterministic CTA reduction of loglik partial.
    __syncthreads();
    red[tid] = la0 + la1;
    __syncthreads();
    for (int off = 256; off > 0; off >>= 1) {
        if (tid < off) red[tid] += red[tid + off];
        __syncthreads();
    }
    if (tid == 0) {
        g_partLL[blockIdx.x] = red[0];
        __threadfence();
    }
    __syncthreads();

    // ---- Last CTA: final deterministic double sum + exact -NTIME*sum(Mu0).
    __shared__ unsigned lastFlag;
    if (tid == 0) lastFlag = atomicAdd(&g_gemmCnt, 1);
    __syncthreads();
    if (lastFlag == GRID - 1) {
        double* dred = (double*)epi;
        double s = (tid < GRID) ? (double)g_partLL[tid] : 0.0;
        if (tid < 256) s -= 65536.0 * (double)Mu0s[tid];
        dred[tid] = s;
        __syncthreads();
        for (int off = 256; off > 0; off >>= 1) {
            if (tid < off) dred[tid] += dred[tid + off];
            __syncthreads();
        }
        if (tid == 0) { out[0] = (float)dred[0]; g_gemmCnt = 0; }
    }
}

// ---------------------------------------------------------------------------
extern "C" void kernel_launch(void* const* d_in, const int* in_sizes, int n_in,
                              void* d_out, int out_size) {
    const float* obs   = (const float*)d_in[0];   // [K, N]
    const float* Beta  = (const float*)d_in[1];   // [K]
    const float* Alpha = (const float*)d_in[2];   // [K, K]
    float* out = (float*)d_out;                   // [1 + K*N + K*N]

    scan_kernel<<<NCHUNK, 256>>>(obs, Beta);

    cudaFuncSetAttribute(gemm_kernel, cudaFuncAttributeMaxDynamicSharedMemorySize, SMEM_BYTES);
    gemm_kernel<<<GRID, 512, SMEM_BYTES>>>(obs, Alpha, out);
}